// round 4
// baseline (speedup 1.0000x reference)
#include <cuda_runtime.h>
#include <cuda_bf16.h>

#define BEV_H 512
#define BEV_W 512
#define BEV_C 64
#define HW (BEV_H * BEV_W)   // 262144 = 2^18
#define TILE 128             // cells per gather block
#define GTHREADS 512

// Scratch: last-writer pillar index per BEV cell (up to 8 batches).
__device__ int g_last[8 * HW];
// Zero row for empty cells (zero-initialized, never written). 16B aligned.
__device__ __align__(16) float g_zero[BEV_C];
// DCE guard for the L2 prefetch sweep.
__device__ float g_sink;

// ---------------------------------------------------------------------------
// Fused: (a) stream feats through L2 so it is L2-resident for the gather,
//        (b) scatter last-occurrence-wins pillar indices via atomicMax.
// ---------------------------------------------------------------------------
__global__ void __launch_bounds__(512) bev_scatter_prefetch_kernel(
    const int* __restrict__ coords,
    const float4* __restrict__ feats4,
    int P, int nf4) {
    const int t = blockIdx.x * blockDim.x + threadIdx.x;
    const int nthreads = gridDim.x * blockDim.x;

    // ---- L2 prefetch sweep over feats (coalesced, grid-strided) ----
    float acc = 0.0f;
#pragma unroll 4
    for (int i = t; i < nf4; i += nthreads) {
        float4 v = __ldg(feats4 + i);
        acc += v.x + v.y + v.z + v.w;
    }
    if (acc == 1.234567e30f) g_sink = acc;  // never true; defeats DCE

    // ---- scatter (first P/4 threads) ----
    int p0 = t * 4;
    if (p0 + 3 < P) {
        const int4* c4 = reinterpret_cast<const int4*>(coords + p0 * 3);
        int4 a  = __ldg(c4 + 0);  // b0 r0 c0 b1
        int4 bb = __ldg(c4 + 1);  // r1 c1 b2 r2
        int4 cc = __ldg(c4 + 2);  // c2 b3 r3 c3
        int bs[4] = {a.x, a.w, bb.z, cc.y};
        int rs[4] = {a.y, bb.x, bb.w, cc.z};
        int cs[4] = {a.z, bb.y, cc.x, cc.w};
#pragma unroll
        for (int k = 0; k < 4; k++) {
            int r = min(max(rs[k], 0), BEV_H - 1);
            int c = min(max(cs[k], 0), BEV_W - 1);
            atomicMax(&g_last[bs[k] * HW + r * BEV_W + c], p0 + k);
        }
    } else if (p0 < P) {
        for (int p = p0; p < P; p++) {
            int b = coords[3 * p + 0];
            int r = min(max(coords[3 * p + 1], 0), BEV_H - 1);
            int c = min(max(coords[3 * p + 2], 0), BEV_W - 1);
            atomicMax(&g_last[b * HW + r * BEV_W + c], p);
        }
    }
}

// ---------------------------------------------------------------------------
// Gather + transpose. 512 threads, TILE=128 cells, 32KB smem (4 CTAs/SM).
// Phase 1: 4-lane teams per cell stage rows into smem with XOR swizzle.
// Phase 2: float4 stores along W with __stcs (evict-first) so the 256MB
//          write stream does not evict the L2-resident feats.
// smem word(ch, cell) = ch*TILE + (cell ^ (q(ch) << 3)),  q(ch) = (ch>>2)&3.
// ---------------------------------------------------------------------------
__global__ void __launch_bounds__(GTHREADS) bev_gather_kernel(
    const float* __restrict__ feats,
    float* __restrict__ out) {
    __shared__ float smem[BEV_C * TILE];  // 32KB

    const int tid = threadIdx.x;
    const int tile_base = blockIdx.x * TILE;   // never crosses a batch
    const int b = tile_base >> 18;
    const int pos_base = tile_base & (HW - 1);

    const int q  = tid & 3;     // lane quarter within the 4-lane row team
    const int cw = tid >> 2;    // 0..127: cell within tile

    // ---- Phase 1: gather rows (L2 hits), stage transposed into smem ----
    {
        const int last = __ldg(&g_last[tile_base + cw]);
        const float4* row = reinterpret_cast<const float4*>(
            last >= 0 ? feats + (size_t)last * BEV_C : g_zero);

        float4 v0 = __ldg(row + q + 0);
        float4 v1 = __ldg(row + q + 4);
        float4 v2 = __ldg(row + q + 8);
        float4 v3 = __ldg(row + q + 12);

        const int csw = cw ^ (q << 3);  // swizzled cell index
        float* s0 = smem + (4 * (q + 0))  * TILE + csw;
        float* s1 = smem + (4 * (q + 4))  * TILE + csw;
        float* s2 = smem + (4 * (q + 8))  * TILE + csw;
        float* s3 = smem + (4 * (q + 12)) * TILE + csw;
        s0[0 * TILE] = v0.x; s0[1 * TILE] = v0.y; s0[2 * TILE] = v0.z; s0[3 * TILE] = v0.w;
        s1[0 * TILE] = v1.x; s1[1 * TILE] = v1.y; s1[2 * TILE] = v1.z; s1[3 * TILE] = v1.w;
        s2[0 * TILE] = v2.x; s2[1 * TILE] = v2.y; s2[2 * TILE] = v2.z; s2[3 * TILE] = v2.w;
        s3[0 * TILE] = v3.x; s3[1 * TILE] = v3.y; s3[2 * TILE] = v3.z; s3[3 * TILE] = v3.w;
    }

    __syncthreads();

    // ---- Phase 2: float4 streaming stores along W ----
    float* out_b = out + (size_t)b * BEV_C * HW + pos_base;
#pragma unroll
    for (int it = 0; it < (BEV_C * TILE / 4) / GTHREADS; it++) {  // 4 iters
        const int idx  = it * GTHREADS + tid;  // quad index 0..2047
        const int ch   = idx >> 5;             // 0..63, constant across a warp
        const int quad = idx & 31;             // warp-contiguous
        const int qq   = (ch >> 2) & 3;
        const int quad_sw = quad ^ (qq << 1);
        float4 v = *reinterpret_cast<const float4*>(smem + ch * TILE + quad_sw * 4);
        __stcs(reinterpret_cast<float4*>(out_b + (size_t)ch * HW + quad * 4), v);
    }
}

extern "C" void kernel_launch(void* const* d_in, const int* in_sizes, int n_in,
                              void* d_out, int out_size) {
    const float* feats  = (const float*)d_in[0];   // (P, 64) float32
    const int*   coords = (const int*)d_in[1];     // (P, 3) int32
    float*       out    = (float*)d_out;           // (B, 64, 512, 512) float32

    int P = in_sizes[0] / BEV_C;
    int nf4 = in_sizes[0] / 4;                     // feats as float4 count
    int B = out_size / (BEV_C * HW);
    if (B > 8) B = 8;
    int ncells = B * HW;

    // 1) init last-index grid to -1 (memset node; 0xFF bytes == -1 int)
    void* lastPtr = nullptr;
    cudaGetSymbolAddress(&lastPtr, g_last);
    cudaMemsetAsync(lastPtr, 0xFF, (size_t)ncells * sizeof(int), 0);

    // 2) fused L2-prefetch of feats + scatter
    int sblocks = 1280;  // 655k threads: ~5 prefetch float4s each; covers P/4 scatter
    int need = ((P + 3) / 4 + 511) / 512;
    if (sblocks < need) sblocks = need;
    bev_scatter_prefetch_kernel<<<sblocks, 512>>>(
        coords, reinterpret_cast<const float4*>(feats), P, nf4);

    // 3) gather + transpose
    bev_gather_kernel<<<ncells / TILE, GTHREADS>>>(feats, out);
}